// round 5
// baseline (speedup 1.0000x reference)
#include <cuda_runtime.h>
#include <cuda_bf16.h>
#include <math_constants.h>

// Fused greedy CTC decode:
//   index[t] = argmax_v emission[t, v]  (first occurrence on ties)
//   char[t]  = -1 if index==0 ; index-1 if index>1 ; 0 if index==1
//   keep[t]  = (char[t] != char[t-1]) && (char[t] != -1)   (char[-1] := -2)
// Output (float32): [0..T) = (float)index, [T..2T) = keep (0.0/1.0).
//
// Block owns 64 consecutive rows (8 warps x 8 rows). Per-row char staged in
// smem; last warp redundantly argmaxes the row preceding the block
// (redundant HBM: 1/64 = +1.6%). Two rows per iteration with all 8 float4
// loads front-batched (MLP=8); warp argmax via REDUX (monotone key trick).

static constexpr int V = 512;
static constexpr int WARPS = 8;
static constexpr int R = 8;                         // rows per warp
static constexpr int ROWS_PER_BLOCK = WARPS * R;    // 64

// Strictly monotone float -> uint map (order-preserving, equality-preserving).
__device__ __forceinline__ unsigned mono(float f)
{
    unsigned u = __float_as_uint(f);
    return u ^ ((unsigned)((int)u >> 31) | 0x80000000u);
}

__device__ __forceinline__ void cmp4(const float4 v, int e, float& best, int& bidx)
{
    if (v.x > best) { best = v.x; bidx = e;     }
    if (v.y > best) { best = v.y; bidx = e + 1; }
    if (v.z > best) { best = v.z; bidx = e + 2; }
    if (v.w > best) { best = v.w; bidx = e + 3; }
}

// Warp argmax of per-lane (best,bidx): max value, min index on ties.
__device__ __forceinline__ int warp_argmax_reduce(float best, int bidx)
{
    const unsigned k = mono(best);
    const unsigned m = __reduce_max_sync(0xFFFFFFFFu, k);
    const unsigned cand = (k == m) ? (unsigned)bidx : 0x7FFFFFFFu;
    return (int)__reduce_min_sync(0xFFFFFFFFu, cand);
}

__device__ __forceinline__ int warp_argmax_row(const float* __restrict__ em,
                                               int row, int lane)
{
    const float4* __restrict__ p =
        reinterpret_cast<const float4*>(em + (size_t)row * V);
    float best = -CUDART_INF_F;
    int   bidx = 0;
#pragma unroll
    for (int c = 0; c < 4; ++c)
        cmp4(p[lane + c * 32], lane * 4 + c * 128, best, bidx);
    return warp_argmax_reduce(best, bidx);
}

__device__ __forceinline__ int ctc_char(int i)
{
    return (i == 0) ? -1 : ((i > 1) ? i - 1 : 0);
}

__global__ __launch_bounds__(WARPS * 32)
void ctc_fused_kernel(const float* __restrict__ em,
                      float* __restrict__ out_index,
                      float* __restrict__ out_keep,
                      int T)
{
    __shared__ int ch[ROWS_PER_BLOCK + 1];   // ch[0] = char of row base-1

    const int warp = threadIdx.x >> 5;
    const int lane = threadIdx.x & 31;
    const int base = blockIdx.x * ROWS_PER_BLOCK;

    // 8 rows per warp, two at a time with front-batched loads (MLP=8).
#pragma unroll
    for (int j = 0; j < R; j += 2) {
        const int local0 = warp * R + j;
        const int r0 = base + local0;
        const int r1 = r0 + 1;

        const float4* __restrict__ p0 =
            reinterpret_cast<const float4*>(em + (size_t)r0 * V);
        const float4* __restrict__ p1 =
            reinterpret_cast<const float4*>(em + (size_t)r1 * V);

        float4 a[4], b[4];
#pragma unroll
        for (int c = 0; c < 4; ++c) { a[c] = p0[lane + c * 32]; }
#pragma unroll
        for (int c = 0; c < 4; ++c) { b[c] = p1[lane + c * 32]; }

        float best0 = -CUDART_INF_F, best1 = -CUDART_INF_F;
        int   bi0 = 0, bi1 = 0;
#pragma unroll
        for (int c = 0; c < 4; ++c) {
            const int e = lane * 4 + c * 128;
            cmp4(a[c], e, best0, bi0);
            cmp4(b[c], e, best1, bi1);
        }

        const int i0 = warp_argmax_reduce(best0, bi0);
        const int i1 = warp_argmax_reduce(best1, bi1);

        if (lane == 0) {
            out_index[r0] = (float)i0;
            out_index[r1] = (float)i1;
            ch[1 + local0]     = ctc_char(i0);
            ch[1 + local0 + 1] = ctc_char(i1);
        }
    }

    // Last warp resolves the block-boundary predecessor row.
    if (warp == WARPS - 1) {
        if (base == 0) {
            if (lane == 0) ch[0] = -2;               // char[-1] sentinel
        } else {
            const int bi = warp_argmax_row(em, base - 1, lane);
            if (lane == 0) ch[0] = ctc_char(bi);
        }
    }
    __syncthreads();

    if (threadIdx.x < ROWS_PER_BLOCK) {
        const int t = base + threadIdx.x;
        if (t < T) {
            const int c  = ch[threadIdx.x + 1];
            const int pc = ch[threadIdx.x];
            out_keep[t] = (c != pc && c != -1) ? 1.0f : 0.0f;
        }
    }
}

extern "C" void kernel_launch(void* const* d_in, const int* in_sizes, int n_in,
                              void* d_out, int out_size)
{
    const float* em = (const float*)d_in[0];
    const int T = in_sizes[0] / V;           // 65536 (divisible by 64)

    float* out       = (float*)d_out;
    float* out_index = out;
    float* out_keep  = out + T;

    const int grid = T / ROWS_PER_BLOCK;
    ctc_fused_kernel<<<grid, WARPS * 32>>>(em, out_index, out_keep, T);
}

// round 6
// speedup vs baseline: 1.0932x; 1.0932x over previous
#include <cuda_runtime.h>
#include <cuda_bf16.h>
#include <math_constants.h>

// Fused greedy CTC decode:
//   index[t] = argmax_v emission[t, v]  (first occurrence on ties)
//   char[t]  = -1 if index==0 ; index-1 if index>1 ; 0 if index==1
//   keep[t]  = (char[t] != char[t-1]) && (char[t] != -1)   (char[-1] := -2)
// Output (float32): [0..T) = (float)index, [T..2T) = keep (0.0/1.0).
//
// R4 shape (8 warps x 4 rows = 32 rows/block, grid 2048, high occupancy)
// with a shallow argmax: fmaxf tree -> REDUX max on monotone key ->
// independent equality-selects -> REDUX min for first-occurrence index.

static constexpr int V = 512;
static constexpr int WARPS = 8;
static constexpr int R = 4;                         // rows per warp
static constexpr int ROWS_PER_BLOCK = WARPS * R;    // 32

// Strictly monotone float -> uint map (order- and equality-preserving).
__device__ __forceinline__ unsigned mono(float f)
{
    unsigned u = __float_as_uint(f);
    return u ^ ((unsigned)((int)u >> 31) | 0x80000000u);
}

// Inverse of mono().
__device__ __forceinline__ float inv_mono(unsigned k)
{
    unsigned u = k ^ ((~(unsigned)((int)k >> 31)) | 0x80000000u);
    return __uint_as_float(u);
}

// Warp argmax of one row; returns first-occurrence argmax (uniform).
__device__ __forceinline__ int warp_argmax_row(const float* __restrict__ em,
                                               int row, int lane)
{
    const float4* __restrict__ p =
        reinterpret_cast<const float4*>(em + (size_t)row * V);

    // Lane covers elements {lane*4 + c*128 + k}, c=0..3, k=0..3.
    float4 v0 = p[lane];
    float4 v1 = p[lane + 32];
    float4 v2 = p[lane + 64];
    float4 v3 = p[lane + 96];

    // Shallow max tree over the 16 lane-local values (FMA pipe).
    float m01 = fmaxf(fmaxf(v0.x, v0.y), fmaxf(v0.z, v0.w));
    float m23 = fmaxf(fmaxf(v1.x, v1.y), fmaxf(v1.z, v1.w));
    float m45 = fmaxf(fmaxf(v2.x, v2.y), fmaxf(v2.z, v2.w));
    float m67 = fmaxf(fmaxf(v3.x, v3.y), fmaxf(v3.z, v3.w));
    float lmax = fmaxf(fmaxf(m01, m23), fmaxf(m45, m67));

    // Warp max in one REDUX.
    const unsigned wkey = __reduce_max_sync(0xFFFFFFFFu, mono(lmax));
    const float wm = inv_mono(wkey);

    // First-occurrence index: independent equality-selects, then min.
    const int e0 = lane * 4, e1 = e0 + 128, e2 = e0 + 256, e3 = e0 + 384;
    const int BIG = 0x7FFFFFFF;
    int c0 = (v0.x == wm) ? e0     : BIG;
    int c1 = (v0.y == wm) ? e0 + 1 : BIG;
    int c2 = (v0.z == wm) ? e0 + 2 : BIG;
    int c3 = (v0.w == wm) ? e0 + 3 : BIG;
    int c4 = (v1.x == wm) ? e1     : BIG;
    int c5 = (v1.y == wm) ? e1 + 1 : BIG;
    int c6 = (v1.z == wm) ? e1 + 2 : BIG;
    int c7 = (v1.w == wm) ? e1 + 3 : BIG;
    int c8  = (v2.x == wm) ? e2     : BIG;
    int c9  = (v2.y == wm) ? e2 + 1 : BIG;
    int c10 = (v2.z == wm) ? e2 + 2 : BIG;
    int c11 = (v2.w == wm) ? e2 + 3 : BIG;
    int c12 = (v3.x == wm) ? e3     : BIG;
    int c13 = (v3.y == wm) ? e3 + 1 : BIG;
    int c14 = (v3.z == wm) ? e3 + 2 : BIG;
    int c15 = (v3.w == wm) ? e3 + 3 : BIG;

    int a = min(min(min(c0, c1), min(c2, c3)), min(min(c4, c5), min(c6, c7)));
    int b = min(min(min(c8, c9), min(c10, c11)),
                min(min(c12, c13), min(c14, c15)));
    const int cand = min(a, b);

    return (int)__reduce_min_sync(0xFFFFFFFFu, (unsigned)cand);
}

__device__ __forceinline__ int ctc_char(int i)
{
    return (i == 0) ? -1 : ((i > 1) ? i - 1 : 0);
}

__global__ __launch_bounds__(WARPS * 32)
void ctc_fused_kernel(const float* __restrict__ em,
                      float* __restrict__ out_index,
                      float* __restrict__ out_keep,
                      int T)
{
    __shared__ int ch[ROWS_PER_BLOCK + 1];   // ch[0] = char of row base-1

    const int warp = threadIdx.x >> 5;
    const int lane = threadIdx.x & 31;
    const int base = blockIdx.x * ROWS_PER_BLOCK;

#pragma unroll
    for (int j = 0; j < R; ++j) {
        const int local = warp * R + j;
        const int row   = base + local;
        const int bidx  = warp_argmax_row(em, row, lane);
        if (lane == 0) {
            out_index[row] = (float)bidx;
            ch[1 + local]  = ctc_char(bidx);
        }
    }

    // Last warp resolves the block-boundary predecessor row.
    if (warp == WARPS - 1) {
        if (base == 0) {
            if (lane == 0) ch[0] = -2;           // char[-1] sentinel
        } else {
            const int bi = warp_argmax_row(em, base - 1, lane);
            if (lane == 0) ch[0] = ctc_char(bi);
        }
    }
    __syncthreads();

    if (threadIdx.x < ROWS_PER_BLOCK) {
        const int t = base + threadIdx.x;
        if (t < T) {
            const int c  = ch[threadIdx.x + 1];
            const int pc = ch[threadIdx.x];
            out_keep[t] = (c != pc && c != -1) ? 1.0f : 0.0f;
        }
    }
}

extern "C" void kernel_launch(void* const* d_in, const int* in_sizes, int n_in,
                              void* d_out, int out_size)
{
    const float* em = (const float*)d_in[0];
    const int T = in_sizes[0] / V;           // 65536 (divisible by 32)

    float* out       = (float*)d_out;
    float* out_index = out;
    float* out_keep  = out + T;

    const int grid = T / ROWS_PER_BLOCK;     // 2048
    ctc_fused_kernel<<<grid, WARPS * 32>>>(em, out_index, out_keep, T);
}